// round 2
// baseline (speedup 1.0000x reference)
#include <cuda_runtime.h>
#include <cstdint>
#include <math.h>

// ---------------------------------------------------------------------------
// PerturbedSelect: reproduce
//   gumbel = jax.random.gumbel(key(42), (1000, 64, 4096), f32)   [threefry2x32]
//   idx    = argmax(logits + sigma*gumbel, axis=-1)
//   S[k,d] = count(idx==d)/1000 ;  Y = X @ S^T
//
// PRNG_MODE 0: jax_threefry_partitionable=True (default in modern JAX):
//              bits[i] = o0 ^ o1 of threefry((0,42), (hi32(i)=0, lo32(i)=i))
// PRNG_MODE 1: legacy split-halves path (fallback if rel_err is O(1))
// ---------------------------------------------------------------------------
#define PRNG_MODE 0

#define NSAMP 1000
#define KOUT  64
#define DDIM  4096
#define BATCH 2048
#define NROWS (NSAMP * KOUT)          /* 64000 */
#define NHALF 131072000u              /* NROWS*DDIM/2, for legacy mode */

__device__ int   g_argmax[NROWS];
__device__ int   g_counts[KOUT * DDIM];
__device__ float g_St[DDIM * KOUT];
__device__ float g_lmin_, g_lmax_;

static __device__ __forceinline__ uint32_t rotl32(uint32_t x, int d) {
    return __funnelshift_l(x, x, d);
}

// Threefry-2x32, 20 rounds, keys (0, 42) — matches jax threefry2x32 lowering.
static __device__ __forceinline__ void threefry(uint32_t x0, uint32_t x1,
                                                uint32_t& o0, uint32_t& o1) {
    const uint32_t k0 = 0u, k1 = 42u, k2 = 0u ^ 42u ^ 0x1BD11BDAu;
    x0 += k0; x1 += k1;
#define RND(r) { x0 += x1; x1 = rotl32(x1, r); x1 ^= x0; }
    RND(13) RND(15) RND(26) RND(6)
    x0 += k1; x1 += k2 + 1u;
    RND(17) RND(29) RND(16) RND(24)
    x0 += k2; x1 += k0 + 2u;
    RND(13) RND(15) RND(26) RND(6)
    x0 += k0; x1 += k1 + 3u;
    RND(17) RND(29) RND(16) RND(24)
    x0 += k1; x1 += k2 + 4u;
    RND(13) RND(15) RND(26) RND(6)
    x0 += k2; x1 += k0 + 5u;
#undef RND
    o0 = x0; o1 = x1;
}

// Mimic jax: u = max(tiny, ((bits>>9)|0x3f800000 as float) - 1 + tiny);
// g = -log(-log(u)), with each log rounded to f32 (double-log is correctly
// rounded and independent of --use_fast_math).
static __device__ __forceinline__ float gumbel_f32(uint32_t bits) {
    const float tiny = 1.17549435082228751e-38f;
    float f = __uint_as_float((bits >> 9) | 0x3f800000u) - 1.0f;  // exact
    float u = fmaxf(tiny, __fadd_rn(f, tiny));
    float L1 = (float)log((double)u);
    float L2 = (float)log((double)(-L1));
    return -L2;
}

#define SIGMA_F ((float)(10.0 * 0.99998))

// ---------------------------------------------------------------- kernel A
__global__ void reduce_range_kernel(const float* __restrict__ logits) {
    __shared__ float smn[32], smx[32];
    float mn = 3.4e38f, mx = -3.4e38f;
    for (int i = threadIdx.x; i < KOUT * DDIM; i += blockDim.x) {
        float v = logits[i];
        mn = fminf(mn, v); mx = fmaxf(mx, v);
    }
    for (int o = 16; o; o >>= 1) {
        mn = fminf(mn, __shfl_xor_sync(~0u, mn, o));
        mx = fmaxf(mx, __shfl_xor_sync(~0u, mx, o));
    }
    if ((threadIdx.x & 31) == 0) { smn[threadIdx.x >> 5] = mn; smx[threadIdx.x >> 5] = mx; }
    __syncthreads();
    if (threadIdx.x == 0) {
        int nw = blockDim.x >> 5;
        for (int w = 1; w < nw; w++) { mn = fminf(mn, smn[w]); mx = fmaxf(mx, smx[w]); }
        g_lmin_ = mn; g_lmax_ = mx;
    }
}

__global__ void zero_counts_kernel() {
    int i = blockIdx.x * blockDim.x + threadIdx.x;
    if (i < KOUT * DDIM) g_counts[i] = 0;
}

// ---------------------------------------------------------------- kernel B
// One CTA per (sample,k) row. Pass 1: threefry all 4096 bits (registers),
// integer max of 23-bit mantissas. Pass 2: exact f32 eval only for candidates
// inside the (lmax-lmin)/sigma gumbel window below the row max.
#define TPB 256
#define DPT (DDIM / TPB)   /* 16 */

__global__ __launch_bounds__(TPB) void argmax_kernel(const float* __restrict__ logits) {
    const int row = blockIdx.x;
    const int k = row & (KOUT - 1);
    const uint32_t base = (uint32_t)row * (uint32_t)DDIM;   // < 2^32
    const int t = threadIdx.x;

    uint32_t m[DPT];
    uint32_t mymax = 0;
#pragma unroll
    for (int j = 0; j < DPT; j++) {
        uint32_t d = (uint32_t)t * DPT + j;
        uint32_t i = base + d;
        uint32_t o0, o1, b;
#if PRNG_MODE == 0
        threefry(0u, i, o0, o1);
        b = o0 ^ o1;
#else
        if (i < NHALF) { threefry(i, i + NHALF, o0, o1); b = o0; }
        else           { threefry(i - NHALF, i, o0, o1); b = o1; }
#endif
        m[j] = b >> 9;
        mymax = max(mymax, m[j]);
    }

    for (int o = 16; o; o >>= 1) mymax = max(mymax, __shfl_xor_sync(~0u, mymax, o));

    __shared__ uint32_t swm[TPB / 32];
    __shared__ uint32_t s_mt;
    __shared__ unsigned long long s_best;
    if ((t & 31) == 0) swm[t >> 5] = mymax;
    if (t == 0) s_best = 0ull;
    __syncthreads();

    if (t == 0) {
        uint32_t mmax = swm[0];
#pragma unroll
        for (int w = 1; w < TPB / 32; w++) mmax = max(mmax, swm[w]);
        float gmax = gumbel_f32(mmax << 9);
        // candidate window: g >= gmax - (lmax-lmin)/sigma - slack
        double W  = (double)(g_lmax_ - g_lmin_) / (double)SIGMA_F + 2e-3;
        double gt = (double)gmax - W;
        double ut = exp(-exp(-gt));                  // invert gumbel (monotone)
        long long mt = (long long)floor(ut * 8388608.0) - 8;   // conservative
        if (mt < 0) mt = 0;
        if (mt > (long long)mmax) mt = (long long)mmax;        // >=1 candidate
        s_mt = (uint32_t)mt;
    }
    __syncthreads();

    const uint32_t mt = s_mt;
    unsigned long long best = 0ull;
#pragma unroll
    for (int j = 0; j < DPT; j++) {
        if (m[j] >= mt) {
            uint32_t d = (uint32_t)t * DPT + j;
            float g = gumbel_f32(m[j] << 9);
            // z exactly as XLA: separate f32 mul + add (no FMA contraction)
            float z = __fadd_rn(logits[k * DDIM + (int)d], __fmul_rn(SIGMA_F, g));
            uint32_t oz = __float_as_uint(z);
            oz = (oz & 0x80000000u) ? ~oz : (oz | 0x80000000u);  // order-preserving
            // tie -> lowest index wins under max-reduce
            unsigned long long key =
                ((unsigned long long)oz << 32) | (uint32_t)(0xFFFFFFFFu - d);
            best = max(best, key);
        }
    }
    for (int o = 16; o; o >>= 1) best = max(best, __shfl_xor_sync(~0u, best, o));
    if ((t & 31) == 0) atomicMax(&s_best, best);
    __syncthreads();
    if (t == 0)
        g_argmax[row] = (int)(0xFFFFFFFFu - (uint32_t)(s_best & 0xFFFFFFFFu));
}

// ---------------------------------------------------------------- kernel C
__global__ void scatter_counts_kernel() {
    int row = blockIdx.x * blockDim.x + threadIdx.x;
    if (row < NROWS) {
        int k = row & (KOUT - 1);
        atomicAdd(&g_counts[(k << 12) + g_argmax[row]], 1);
    }
}

__global__ void build_st_kernel() {
    int i = blockIdx.x * blockDim.x + threadIdx.x;   // i = k*4096 + d
    if (i < KOUT * DDIM) {
        int k = i >> 12, d = i & (DDIM - 1);
        g_St[d * KOUT + k] = (float)g_counts[i] * 0.001f;
    }
}

// ---------------------------------------------------------------- kernel D
// Y[2048,64] = X[2048,4096] @ St[4096,64].  CTA: 16 rows x 64 k, 128 threads,
// thread tile 2x4, smem-staged, fp32 accumulation.
#define TB_M 16
#define DC   64

__global__ __launch_bounds__(128) void gemm_kernel(const float* __restrict__ X,
                                                   float* __restrict__ Y) {
    __shared__ float Xs[TB_M][DC + 4];
    __shared__ float Ss[DC][KOUT + 4];     // stride 68 floats = 17*16B (aligned)
    const int t = threadIdx.x;
    const int brow0 = blockIdx.x * TB_M;
    const int tr = t >> 4;          // 0..7  -> rows tr*2, tr*2+1
    const int tk = t & 15;          // 0..15 -> cols tk*4 .. tk*4+3
    float acc[2][4] = {};

    for (int d0 = 0; d0 < DDIM; d0 += DC) {
#pragma unroll
        for (int l = 0; l < 8; l++) {          // 16*64 = 1024 floats
            int idx = t + l * 128;
            Xs[idx >> 6][idx & 63] = X[(brow0 + (idx >> 6)) * DDIM + d0 + (idx & 63)];
        }
#pragma unroll
        for (int l = 0; l < 32; l++) {         // 64*64 = 4096 floats
            int idx = t + l * 128;
            Ss[idx >> 6][idx & 63] = g_St[(d0 + (idx >> 6)) * KOUT + (idx & 63)];
        }
        __syncthreads();
#pragma unroll
        for (int dd = 0; dd < DC; dd++) {
            float x0 = Xs[tr * 2 + 0][dd];
            float x1 = Xs[tr * 2 + 1][dd];
            float4 s = *(const float4*)&Ss[dd][tk * 4];
            acc[0][0] += x0 * s.x; acc[0][1] += x0 * s.y;
            acc[0][2] += x0 * s.z; acc[0][3] += x0 * s.w;
            acc[1][0] += x1 * s.x; acc[1][1] += x1 * s.y;
            acc[1][2] += x1 * s.z; acc[1][3] += x1 * s.w;
        }
        __syncthreads();
    }
#pragma unroll
    for (int r = 0; r < 2; r++)
#pragma unroll
        for (int c = 0; c < 4; c++)
            Y[(brow0 + tr * 2 + r) * KOUT + tk * 4 + c] = acc[r][c];
}

// ---------------------------------------------------------------------------
extern "C" void kernel_launch(void* const* d_in, const int* in_sizes, int n_in,
                              void* d_out, int out_size) {
    const float* X = (const float*)d_in[0];
    const float* logits = (const float*)d_in[1];
    if (n_in >= 2 && in_sizes[0] == KOUT * DDIM) {   // defensive: swapped order
        X = (const float*)d_in[1];
        logits = (const float*)d_in[0];
    }
    float* Y = (float*)d_out;

    reduce_range_kernel<<<1, 1024>>>(logits);
    zero_counts_kernel<<<(KOUT * DDIM + 255) / 256, 256>>>();
    argmax_kernel<<<NROWS, TPB>>>(logits);
    scatter_counts_kernel<<<(NROWS + 255) / 256, 256>>>();
    build_st_kernel<<<(KOUT * DDIM + 255) / 256, 256>>>();
    gemm_kernel<<<BATCH / TB_M, 128>>>(X, Y);
}

// round 3
// speedup vs baseline: 1.5720x; 1.5720x over previous
#include <cuda_runtime.h>
#include <cstdint>
#include <math.h>

// ---------------------------------------------------------------------------
// PerturbedSelect (verified R2, rel_err 5.6e-7):
//   bits[i] = o0^o1 of threefry2x32((0,42),(0,i))   [jax partitionable PRNG]
//   g = -log(-log(u(bits))) ; idx = argmax_d logits[k,d] + sigma*g
//   S[k,d] = count/1000 ; Y = X @ S^T
// R3: float (MUFU) candidate threshold, raw-bit compares, fused scatter,
//     parallel range reduction.
// ---------------------------------------------------------------------------

#define NSAMP 1000
#define KOUT  64
#define DDIM  4096
#define BATCH 2048
#define NROWS (NSAMP * KOUT)          /* 64000 */

__device__ int      g_counts[KOUT * DDIM];
__device__ float    g_St[DDIM * KOUT];
__device__ uint32_t g_mn_u, g_mx_u;   // order-preserving encoded float min/max

static __device__ __forceinline__ uint32_t enc_f(float x) {
    uint32_t u = __float_as_uint(x);
    return (u & 0x80000000u) ? ~u : (u | 0x80000000u);
}
static __device__ __forceinline__ float dec_f(uint32_t e) {
    uint32_t u = (e & 0x80000000u) ? (e ^ 0x80000000u) : ~e;
    return __uint_as_float(u);
}

static __device__ __forceinline__ uint32_t rotl32(uint32_t x, int d) {
    return __funnelshift_l(x, x, d);
}

// Threefry-2x32, 20 rounds, key (0, 42) — matches jax threefry2x32 lowering.
static __device__ __forceinline__ void threefry(uint32_t x0, uint32_t x1,
                                                uint32_t& o0, uint32_t& o1) {
    const uint32_t k0 = 0u, k1 = 42u, k2 = 0u ^ 42u ^ 0x1BD11BDAu;
    x0 += k0; x1 += k1;
#define RND(r) { x0 += x1; x1 = rotl32(x1, r); x1 ^= x0; }
    RND(13) RND(15) RND(26) RND(6)
    x0 += k1; x1 += k2 + 1u;
    RND(17) RND(29) RND(16) RND(24)
    x0 += k2; x1 += k0 + 2u;
    RND(13) RND(15) RND(26) RND(6)
    x0 += k0; x1 += k1 + 3u;
    RND(17) RND(29) RND(16) RND(24)
    x0 += k1; x1 += k2 + 4u;
    RND(13) RND(15) RND(26) RND(6)
    x0 += k2; x1 += k0 + 5u;
#undef RND
    o0 = x0; o1 = x1;
}

// Exact jax gumbel from raw bits; double logs are correctly rounded and
// immune to --use_fast_math. Used ONLY for the rare candidates (~1-2/row).
static __device__ __forceinline__ float gumbel_f32(uint32_t bits) {
    const float tiny = 1.17549435082228751e-38f;
    float f = __uint_as_float((bits >> 9) | 0x3f800000u) - 1.0f;  // exact
    float u = fmaxf(tiny, __fadd_rn(f, tiny));
    float L1 = (float)log((double)u);
    float L2 = (float)log((double)(-L1));
    return -L2;
}

#define SIGMA_F ((float)(10.0 * 0.99998))

// ---------------------------------------------------------------- kernel 1
__global__ void zero_init_kernel() {
    int i = blockIdx.x * blockDim.x + threadIdx.x;
    if (i < KOUT * DDIM) g_counts[i] = 0;
    if (i == 0) { g_mx_u = 0u; g_mn_u = 0xFFFFFFFFu; }
}

// ---------------------------------------------------------------- kernel 2
__global__ void range_kernel(const float* __restrict__ logits) {
    float mn = 3.4e38f, mx = -3.4e38f;
    for (int i = blockIdx.x * blockDim.x + threadIdx.x; i < KOUT * DDIM;
         i += gridDim.x * blockDim.x) {
        float v = logits[i];
        mn = fminf(mn, v); mx = fmaxf(mx, v);
    }
    for (int o = 16; o; o >>= 1) {
        mn = fminf(mn, __shfl_xor_sync(~0u, mn, o));
        mx = fmaxf(mx, __shfl_xor_sync(~0u, mx, o));
    }
    if ((threadIdx.x & 31) == 0) {
        atomicMin(&g_mn_u, enc_f(mn));
        atomicMax(&g_mx_u, enc_f(mx));
    }
}

// ---------------------------------------------------------------- kernel 3
// One CTA per (sample,k) row. Pass 1: threefry all 4096 bits into registers,
// integer max over raw bits. Threshold (float MUFU, conservative) selects
// ~1-2 candidates/row for exact evaluation; winner counted via atomicAdd.
#define TPB 256
#define DPT (DDIM / TPB)   /* 16 */

__global__ __launch_bounds__(TPB) void argmax_kernel(const float* __restrict__ logits) {
    const int row = blockIdx.x;
    const int k = row & (KOUT - 1);
    const uint32_t base = (uint32_t)row * (uint32_t)DDIM;   // < 2^32
    const int t = threadIdx.x;

    uint32_t m[DPT];
#pragma unroll
    for (int j = 0; j < DPT; j++) {
        uint32_t i = base + (uint32_t)t * DPT + j;
        uint32_t o0, o1;
        threefry(0u, i, o0, o1);
        m[j] = o0 ^ o1;                 // raw 32-bit; compare order == m>>9 order
    }

    // tree max for ILP
    uint32_t r8[8];
#pragma unroll
    for (int j = 0; j < 8; j++) r8[j] = max(m[j], m[j + 8]);
#pragma unroll
    for (int j = 0; j < 4; j++) r8[j] = max(r8[j], r8[j + 4]);
    uint32_t mymax = max(max(r8[0], r8[1]), max(r8[2], r8[3]));

    for (int o = 16; o; o >>= 1) mymax = max(mymax, __shfl_xor_sync(~0u, mymax, o));

    __shared__ uint32_t swm[TPB / 32];
    __shared__ uint32_t s_mt9;
    __shared__ unsigned long long s_best;
    if ((t & 31) == 0) swm[t >> 5] = mymax;
    if (t == 0) s_best = 0ull;
    __syncthreads();

    if (t == 0) {
        uint32_t mmax = swm[0];
#pragma unroll
        for (int w = 1; w < TPB / 32; w++) mmax = max(mmax, swm[w]);
        uint32_t mm9 = mmax >> 9;
        // Candidate window in u-space: u_t = u_max^{exp(W)}, W = range/sigma + slack.
        // MUFU-fast with 64-tick downward slack: threshold is only a pruning
        // bound — pass-2 exact eval decides the argmax.
        float W  = (dec_f(g_mx_u) - dec_f(g_mn_u)) * (1.0f / SIGMA_F) + 2e-3f;
        float um = fmaxf(__uint_as_float(mm9 | 0x3f800000u) - 1.0f, 1e-30f);
        float ut = __expf(__expf(W) * __logf(um));
        long long mt = (long long)floorf(ut * 8388608.0f) - 64;
        if (mt < 0) mt = 0;
        if ((unsigned long long)mt > mm9) mt = mm9;
        s_mt9 = (uint32_t)mt << 9;
    }
    __syncthreads();

    const uint32_t mt9 = s_mt9;
    unsigned long long best = 0ull;
#pragma unroll
    for (int j = 0; j < DPT; j++) {
        if (m[j] >= mt9) {
            uint32_t d = (uint32_t)t * DPT + j;
            float g = gumbel_f32(m[j]);
            // z exactly as XLA: separate f32 mul + add (no FMA contraction)
            float z = __fadd_rn(logits[k * DDIM + (int)d], __fmul_rn(SIGMA_F, g));
            uint32_t oz = __float_as_uint(z);
            oz = (oz & 0x80000000u) ? ~oz : (oz | 0x80000000u);  // order-preserving
            unsigned long long key =
                ((unsigned long long)oz << 32) | (uint32_t)(0xFFFFFFFFu - d);
            best = max(best, key);   // tie -> lowest index wins
        }
    }
    for (int o = 16; o; o >>= 1) best = max(best, __shfl_xor_sync(~0u, best, o));
    if ((t & 31) == 0) atomicMax(&s_best, best);
    __syncthreads();
    if (t == 0) {
        int d = (int)(0xFFFFFFFFu - (uint32_t)(s_best & 0xFFFFFFFFu));
        atomicAdd(&g_counts[(k << 12) + d], 1);
    }
}

// ---------------------------------------------------------------- kernel 4
__global__ void build_st_kernel() {
    int i = blockIdx.x * blockDim.x + threadIdx.x;   // i = k*4096 + d
    if (i < KOUT * DDIM) {
        int k = i >> 12, d = i & (DDIM - 1);
        g_St[d * KOUT + k] = (float)g_counts[i] * 0.001f;
    }
}

// ---------------------------------------------------------------- kernel 5
// Y[2048,64] = X[2048,4096] @ St[4096,64]
#define TB_M 16
#define DC   64

__global__ __launch_bounds__(128) void gemm_kernel(const float* __restrict__ X,
                                                   float* __restrict__ Y) {
    __shared__ float Xs[TB_M][DC + 4];
    __shared__ float Ss[DC][KOUT + 4];
    const int t = threadIdx.x;
    const int brow0 = blockIdx.x * TB_M;
    const int tr = t >> 4;          // 0..7  -> rows tr*2, tr*2+1
    const int tk = t & 15;          // 0..15 -> cols tk*4 .. tk*4+3
    float acc[2][4] = {};

    for (int d0 = 0; d0 < DDIM; d0 += DC) {
#pragma unroll
        for (int l = 0; l < 8; l++) {
            int idx = t + l * 128;
            Xs[idx >> 6][idx & 63] = X[(brow0 + (idx >> 6)) * DDIM + d0 + (idx & 63)];
        }
#pragma unroll
        for (int l = 0; l < 32; l++) {
            int idx = t + l * 128;
            Ss[idx >> 6][idx & 63] = g_St[(d0 + (idx >> 6)) * KOUT + (idx & 63)];
        }
        __syncthreads();
#pragma unroll
        for (int dd = 0; dd < DC; dd++) {
            float x0 = Xs[tr * 2 + 0][dd];
            float x1 = Xs[tr * 2 + 1][dd];
            float4 s = *(const float4*)&Ss[dd][tk * 4];
            acc[0][0] += x0 * s.x; acc[0][1] += x0 * s.y;
            acc[0][2] += x0 * s.z; acc[0][3] += x0 * s.w;
            acc[1][0] += x1 * s.x; acc[1][1] += x1 * s.y;
            acc[1][2] += x1 * s.z; acc[1][3] += x1 * s.w;
        }
        __syncthreads();
    }
#pragma unroll
    for (int r = 0; r < 2; r++)
#pragma unroll
        for (int c = 0; c < 4; c++)
            Y[(brow0 + tr * 2 + r) * KOUT + tk * 4 + c] = acc[r][c];
}

// ---------------------------------------------------------------------------
extern "C" void kernel_launch(void* const* d_in, const int* in_sizes, int n_in,
                              void* d_out, int out_size) {
    const float* X = (const float*)d_in[0];
    const float* logits = (const float*)d_in[1];
    if (n_in >= 2 && in_sizes[0] == KOUT * DDIM) {   // defensive: swapped order
        X = (const float*)d_in[1];
        logits = (const float*)d_in[0];
    }
    float* Y = (float*)d_out;

    zero_init_kernel<<<(KOUT * DDIM + 255) / 256, 256>>>();
    range_kernel<<<64, 256>>>(logits);
    argmax_kernel<<<NROWS, TPB>>>(logits);
    build_st_kernel<<<(KOUT * DDIM + 255) / 256, 256>>>();
    gemm_kernel<<<BATCH / TB_M, 128>>>(X, Y);
}